// round 3
// baseline (speedup 1.0000x reference)
#include <cuda_runtime.h>

#define BATCH 256
#define NROWS 256
#define MCOLS 256
#define DDIM  32
#define TPB   128                    // 4 warps, 2 rows per thread
#define NWARP 4
#define STEPS (MCOLS + TPB - 1)      // 383
#define LOG2E 1.4426950408889634f
#define BIGF  (1e8f * LOG2E)         // boundary in scaled domain

__device__ float g_part[BATCH];
__device__ int   g_count;

typedef unsigned long long u64;

#define FMA_F32X2(d, a, b) \
    asm("fma.rn.f32x2 %0, %1, %2, %0;" : "+l"(d) : "l"(a), "l"(b))
#define PACK_F32X2(out, lo, hi) \
    asm("mov.b64 %0, {%1, %2};" : "=l"(out) : "f"(lo), "f"(hi))
#define UNPACK_F32X2(lo, hi, in) \
    asm("mov.b64 {%0, %1}, %2;" : "=f"(lo), "=f"(hi) : "l"(in))

__device__ __forceinline__ float ex2f(float x) {
    float r; asm("ex2.approx.f32 %0, %1;" : "=f"(r) : "f"(x)); return r;
}
__device__ __forceinline__ float lg2f(float x) {
    float r; asm("lg2.approx.f32 %0, %1;" : "=f"(r) : "f"(x)); return r;
}

// softmin in the D*log2e scaled domain: mn - log2(2^(mn-a)+2^(mn-b)+2^(mn-c))
__device__ __forceinline__ float softmin3s(float a, float b, float c) {
    float mn = fminf(fminf(a, b), c);
    float s  = ex2f(mn - a) + ex2f(mn - b) + ex2f(mn - c);
    return mn - lg2f(s);
}

__global__ __launch_bounds__(TPB)
void sdtw_kernel(const float* __restrict__ X, const float* __restrict__ Y,
                 float* __restrict__ out) {
    // y chunks transposed: sy4[c][j], pad 257 float4s to avoid bank conflicts
    __shared__ float4 sy4[8 * 257];
    __shared__ float  sy2[MCOLS];               // ||y_j||^2 * log2e
    __shared__ u64    ring[NWARP - 1][STEPS];   // cross-warp handoff, tagged words
    __shared__ float  red[TPB];
    __shared__ int    islast;

    const int t    = threadIdx.x;
    const int lane = t & 31;
    const int w    = t >> 5;
    const int b    = blockIdx.x;
    const float* xb = X + (size_t)b * NROWS * DDIM;
    const float* yb = Y + (size_t)b * MCOLS * DDIM;

    // ---- stage y (chunk-transposed), coalesced ----
    const float4* yb4 = (const float4*)yb;
    for (int k = t; k < MCOLS * 8; k += TPB) {
        int j = k >> 3, c = k & 7;
        sy4[c * 257 + j] = yb4[k];
    }
    // ---- scaled y squared norms ----
    for (int j = t; j < MCOLS; j += TPB) {
        const float4* row = (const float4*)(yb + j * DDIM);
        float acc = 0.f;
        #pragma unroll
        for (int c = 0; c < 8; c++) {
            float4 v = row[c];
            acc += v.x * v.x + v.y * v.y + v.z * v.z + v.w * v.w;
        }
        sy2[j] = acc * LOG2E;
    }
    // ---- zero handoff tags ----
    for (int k = t; k < (NWARP - 1) * STEPS; k += TPB)
        ((u64*)ring)[k] = 0ull;

    // ---- this thread's 2 x-rows, packed f32x2 ----
    u64 ax0[16], ax1[16];
    float xx0 = 0.f, xx1 = 0.f;
    {
        const float4* r0 = (const float4*)(xb + (size_t)(2 * t)     * DDIM);
        const float4* r1 = (const float4*)(xb + (size_t)(2 * t + 1) * DDIM);
        #pragma unroll
        for (int c = 0; c < 8; c++) {
            float4 v0 = r0[c], v1r = r1[c];
            PACK_F32X2(ax0[2*c],   v0.x,  v0.y);
            PACK_F32X2(ax0[2*c+1], v0.z,  v0.w);
            PACK_F32X2(ax1[2*c],   v1r.x, v1r.y);
            PACK_F32X2(ax1[2*c+1], v1r.z, v1r.w);
            xx0 += v0.x*v0.x + v0.y*v0.y + v0.z*v0.z + v0.w*v0.w;
            xx1 += v1r.x*v1r.x + v1r.y*v1r.y + v1r.z*v1r.z + v1r.w*v1r.w;
        }
    }
    xx0 *= LOG2E; xx1 *= LOG2E;
    __syncthreads();   // one-time: smem staging done

    // ---- DP state (scaled domain) ----
    float left0 = BIGF, left1 = BIGF;
    float tl = (t == 0) ? 0.f : BIGF;
    float v1 = BIGF;                        // last step's bottom-row value

    volatile u64* myring  = (w < NWARP - 1) ? &ring[w][0]     : 0;
    volatile u64* upring  = (w > 0)         ? &ring[w - 1][0] : 0;

    #pragma unroll 2
    for (int s = 0; s < STEPS; s++) {
        const int jj = s - t;
        // neighbor's bottom value from previous step (same column index)
        float up_sh = __shfl_up_sync(0xffffffffu, v1, 1);
        const bool active = (jj >= 0) && (jj < MCOLS);

        if (active) {
            float up0;
            if (lane == 0) {
                if (w == 0) {
                    up0 = BIGF;
                } else {
                    u64 word;
                    do { word = upring[s - 1]; } while ((unsigned)(word >> 32) != (unsigned)s);
                    up0 = __uint_as_float((unsigned)word);
                }
            } else {
                up0 = up_sh;
            }

            // packed-f32x2 dots for both rows
            u64 a0 = 0ull, b0 = 0ull, a1 = 0ull, b1 = 0ull;
            #pragma unroll
            for (int c = 0; c < 8; c++) {
                float4 ya = sy4[c * 257 + jj];
                u64 ylo, yhi;
                PACK_F32X2(ylo, ya.x, ya.y);
                PACK_F32X2(yhi, ya.z, ya.w);
                FMA_F32X2(a0, ax0[2*c],   ylo);
                FMA_F32X2(b0, ax0[2*c+1], yhi);
                FMA_F32X2(a1, ax1[2*c],   ylo);
                FMA_F32X2(b1, ax1[2*c+1], yhi);
            }
            float l0,h0,l0b,h0b,l1,h1,l1b,h1b;
            UNPACK_F32X2(l0,  h0,  a0);
            UNPACK_F32X2(l0b, h0b, b0);
            UNPACK_F32X2(l1,  h1,  a1);
            UNPACK_F32X2(l1b, h1b, b1);
            float dot0 = (l0 + h0) + (l0b + h0b);
            float dot1 = (l1 + h1) + (l1b + h1b);

            float syy = sy2[jj];
            float dist0 = fmaxf(fmaf(dot0, -2.f * LOG2E, xx0 + syy), 0.f);
            float dist1 = fmaxf(fmaf(dot1, -2.f * LOG2E, xx1 + syy), 0.f);

            float v0 = dist0 + softmin3s(up0, left0, tl);
            float nv1 = dist1 + softmin3s(v0,  left1, left0);
            tl = up0; left0 = v0; left1 = nv1;
            v1 = nv1;

            if (lane == 31 && w < NWARP - 1)
                myring[s] = ((u64)(unsigned)(s + 1) << 32) | (u64)__float_as_uint(nv1);

            if (t == TPB - 1 && jj == MCOLS - 1)
                g_part[b] = nv1;            // scaled D[N][M]
        }
    }

    // ---- fused grid reduction (last CTA) ----
    __threadfence();
    __syncthreads();
    if (t == 0) islast = (atomicAdd(&g_count, 1) == BATCH - 1);
    __syncthreads();
    if (islast) {
        __threadfence();
        float v = g_part[t] + g_part[t + TPB];
        red[t] = v;
        __syncthreads();
        #pragma unroll
        for (int o = TPB / 2; o > 0; o >>= 1) {
            if (t < o) red[t] += red[t + o];
            __syncthreads();
        }
        if (t == 0) {
            out[0] = red[0] * (1.0f / ((float)BATCH * LOG2E));
            g_count = 0;                    // reset for next graph replay
        }
    }
}

extern "C" void kernel_launch(void* const* d_in, const int* in_sizes, int n_in,
                              void* d_out, int out_size) {
    const float* x = (const float*)d_in[0];
    const float* y = (const float*)d_in[1];
    float* out = (float*)d_out;
    sdtw_kernel<<<BATCH, TPB>>>(x, y, out);
}

// round 4
// speedup vs baseline: 1.8207x; 1.8207x over previous
#include <cuda_runtime.h>

#define BATCH 256
#define NROWS 256
#define MCOLS 256
#define DDIM  32
#define TPB   128                    // 4 warps, 2 DP rows per thread
#define NWARP 4
#define EXSKEW 16                    // extra pipeline skew per warp (steps)
#define OMAX  (TPB - 1 + EXSKEW * (NWARP - 1))   // 175
#define STEPS (MCOLS + OMAX)                     // 431
#define LOG2E 1.4426950408889634f
#define BIGF  (1e8f * LOG2E)         // boundary in scaled (D*log2e) domain

__device__ float g_part[BATCH];
__device__ int   g_count;

typedef unsigned long long u64;

#define FMA_F32X2(d, a, b) \
    asm("fma.rn.f32x2 %0, %1, %2, %0;" : "+l"(d) : "l"(a), "l"(b))
#define PACK_F32X2(out, lo, hi) \
    asm("mov.b64 %0, {%1, %2};" : "=l"(out) : "f"(lo), "f"(hi))
#define UNPACK_F32X2(lo, hi, in) \
    asm("mov.b64 {%0, %1}, %2;" : "=f"(lo), "=f"(hi) : "l"(in))

__device__ __forceinline__ float ex2f(float x) {
    float r; asm("ex2.approx.f32 %0, %1;" : "=f"(r) : "f"(x)); return r;
}
__device__ __forceinline__ float lg2f(float x) {
    float r; asm("lg2.approx.f32 %0, %1;" : "=f"(r) : "f"(x)); return r;
}

// softmin in the scaled domain: mn - log2(2^(mn-a)+2^(mn-b)+2^(mn-c))
__device__ __forceinline__ float softmin3s(float a, float b, float c) {
    float mn = fminf(fminf(a, b), c);
    float s  = ex2f(mn - a) + ex2f(mn - b) + ex2f(mn - c);
    return mn - lg2f(s);
}

__global__ __launch_bounds__(TPB)
void sdtw_kernel(const float* __restrict__ X, const float* __restrict__ Y,
                 float* __restrict__ out) {
    // y chunk-transposed: sy4[c][j] (16B each), pad 257 to kill bank conflicts
    __shared__ ulonglong2 sy4[8 * 257];
    __shared__ float      sy2[MCOLS];              // ||y_j||^2 * log2e
    __shared__ u64        ring[NWARP - 1][MCOLS];  // per-column tagged handoff
    __shared__ float      red[TPB];
    __shared__ int        islast;

    const int t    = threadIdx.x;
    const int lane = t & 31;
    const int w    = t >> 5;
    const int o    = t + EXSKEW * w;   // this thread's pipeline offset
    const int b    = blockIdx.x;
    const float* xb = X + (size_t)b * NROWS * DDIM;
    const float* yb = Y + (size_t)b * MCOLS * DDIM;

    // ---- stage y (chunk-transposed), coalesced 16B loads ----
    const ulonglong2* yb16 = (const ulonglong2*)yb;
    for (int k = t; k < MCOLS * 8; k += TPB) {
        int j = k >> 3, c = k & 7;
        sy4[c * 257 + j] = yb16[k];
    }
    // ---- scaled y squared norms ----
    for (int j = t; j < MCOLS; j += TPB) {
        const float4* row = (const float4*)(yb + j * DDIM);
        float acc = 0.f;
        #pragma unroll
        for (int c = 0; c < 8; c++) {
            float4 v = row[c];
            acc += v.x * v.x + v.y * v.y + v.z * v.z + v.w * v.w;
        }
        sy2[j] = acc * LOG2E;
    }
    // ---- zero handoff tags ----
    for (int k = t; k < (NWARP - 1) * MCOLS; k += TPB)
        ((u64*)ring)[k] = 0ull;

    // ---- this thread's 2 x-rows, packed f32x2 once ----
    u64 ax0[16], ax1[16];
    float xx0 = 0.f, xx1 = 0.f;
    {
        const float4* r0 = (const float4*)(xb + (size_t)(2 * t)     * DDIM);
        const float4* r1 = (const float4*)(xb + (size_t)(2 * t + 1) * DDIM);
        #pragma unroll
        for (int c = 0; c < 8; c++) {
            float4 v0 = r0[c], v1r = r1[c];
            PACK_F32X2(ax0[2*c],   v0.x,  v0.y);
            PACK_F32X2(ax0[2*c+1], v0.z,  v0.w);
            PACK_F32X2(ax1[2*c],   v1r.x, v1r.y);
            PACK_F32X2(ax1[2*c+1], v1r.z, v1r.w);
            xx0 += v0.x*v0.x + v0.y*v0.y + v0.z*v0.z + v0.w*v0.w;
            xx1 += v1r.x*v1r.x + v1r.y*v1r.y + v1r.z*v1r.z + v1r.w*v1r.w;
        }
    }
    xx0 *= LOG2E; xx1 *= LOG2E;
    __syncthreads();   // one-time: smem staging complete

    // ---- DP state (scaled domain) ----
    float left0 = BIGF, left1 = BIGF;
    float tl = (t == 0) ? 0.f : BIGF;
    float v1 = BIGF;                       // last-step bottom-row value

    volatile u64* myring = (w < NWARP - 1) ? &ring[w][0]     : 0;
    volatile u64* upring = (w > 0)         ? &ring[w - 1][0] : 0;

    #pragma unroll 1
    for (int s = 0; s < STEPS; s++) {
        // neighbor's prev-step bottom value (must be warp-uniform exec)
        float up_sh = __shfl_up_sync(0xffffffffu, v1, 1);
        const int jj = s - o;
        if (jj >= 0 && jj < MCOLS) {
            // ---- 1) distances first (independent of DP chain) ----
            u64 a0 = 0ull, b0 = 0ull, a1 = 0ull, b1 = 0ull;
            #pragma unroll
            for (int c = 0; c < 8; c++) {
                ulonglong2 yv = sy4[c * 257 + jj];   // LDS.128; halves alias as f32x2
                FMA_F32X2(a0, ax0[2*c],   yv.x);
                FMA_F32X2(b0, ax0[2*c+1], yv.y);
                FMA_F32X2(a1, ax1[2*c],   yv.x);
                FMA_F32X2(b1, ax1[2*c+1], yv.y);
            }
            float l0,h0,l0b,h0b,l1,h1,l1b,h1b;
            UNPACK_F32X2(l0,  h0,  a0);
            UNPACK_F32X2(l0b, h0b, b0);
            UNPACK_F32X2(l1,  h1,  a1);
            UNPACK_F32X2(l1b, h1b, b1);
            float dot0 = (l0 + h0) + (l0b + h0b);
            float dot1 = (l1 + h1) + (l1b + h1b);
            float syy  = sy2[jj];
            float dist0 = fmaxf(fmaf(dot0, -2.f * LOG2E, xx0 + syy), 0.f);
            float dist1 = fmaxf(fmaf(dot1, -2.f * LOG2E, xx1 + syy), 0.f);

            // ---- 2) handoff read (17 steps of slack -> first-try hit) ----
            float up0;
            if (lane == 0) {
                if (w == 0) {
                    up0 = BIGF;
                } else {
                    u64 word = upring[jj];
                    while ((unsigned)(word >> 32) != (unsigned)(jj + 1))
                        word = upring[jj];
                    up0 = __uint_as_float((unsigned)word);
                }
            } else {
                up0 = up_sh;
            }

            // ---- 3) serial 2-cell softmin chain ----
            float v0  = dist0 + softmin3s(up0, left0, tl);
            float nv1 = dist1 + softmin3s(v0,  left1, left0);
            tl = up0; left0 = v0; left1 = nv1;
            v1 = nv1;

            if (lane == 31 && w < NWARP - 1)
                myring[jj] = ((u64)(unsigned)(jj + 1) << 32) | (u64)__float_as_uint(nv1);

            if (t == TPB - 1 && jj == MCOLS - 1)
                g_part[b] = nv1;           // scaled D[N][M]
        }
    }

    // ---- fused grid reduction (last CTA) ----
    __threadfence();
    __syncthreads();
    if (t == 0) islast = (atomicAdd(&g_count, 1) == BATCH - 1);
    __syncthreads();
    if (islast) {
        __threadfence();
        red[t] = g_part[t] + g_part[t + TPB];
        __syncthreads();
        #pragma unroll
        for (int off = TPB / 2; off > 0; off >>= 1) {
            if (t < off) red[t] += red[t + off];
            __syncthreads();
        }
        if (t == 0) {
            out[0] = red[0] * (1.0f / ((float)BATCH * LOG2E));
            g_count = 0;                   // reset for next graph replay
        }
    }
}

extern "C" void kernel_launch(void* const* d_in, const int* in_sizes, int n_in,
                              void* d_out, int out_size) {
    const float* x = (const float*)d_in[0];
    const float* y = (const float*)d_in[1];
    float* out = (float*)d_out;
    sdtw_kernel<<<BATCH, TPB>>>(x, y, out);
}